// round 8
// baseline (speedup 1.0000x reference)
#include <cuda_runtime.h>
#include <cstdint>

// Problem constants
constexpr int KC = 5, PC = 2, BC = 2, NC = 8, HC = 512, WC = 512;

// Full-width tiles: 4 rows x 512 cols (one contiguous 8KB core-plane block
// per tile per k). Register-slim body (window row loaded from smem per i)
// so we fit 3 CTAs/SM -> 1536 threads/SM, 50% more warps issuing LDGs.
constexpr int TH = 4;
constexpr int SWP = 520;             // padded row pitch (floats), 16B aligned
constexpr int NT = 512;              // threads per CTA
constexpr int TILES_Y = HC / TH;     // 128 row-tiles
constexpr int N_TILES = TILES_Y * BC * NC;   // 2048
constexpr int OCC = 3;               // CTAs per SM
constexpr int GRID = 152 * OCC;      // 456 persistent CTAs
constexpr int SH = TH + 2 * PC;      // 8 staged rows
constexpr int SBUF = SH * SWP;       // 4160 floats per buffer

__device__ int g_next;

__global__ void init_counter() { g_next = GRID; }

// cp.async 4B with zero-fill when !ok (src-size 0 -> no global read, zeros)
__device__ __forceinline__ void cp4(uint32_t dst, const float* src, bool ok) {
    asm volatile("cp.async.ca.shared.global [%0], [%1], 4, %2;\n"
                 :: "r"(dst), "l"(src), "r"(ok ? 4 : 0));
}

__global__ __launch_bounds__(NT, OCC)
void kconv_kernel(const float* __restrict__ frames,
                  const float* __restrict__ core,
                  const float* __restrict__ Wt,
                  float* __restrict__ out)
{
    __shared__ float s[2][SBUF];
    __shared__ int s_next;

    const size_t plane = (size_t)HC * WC;
    const uint32_t sbase = (uint32_t)__cvta_generic_to_shared(&s[0][0]);

    // ---- async stage of one padded 8x520 frame strip into a smem buffer ----
    auto stage = [&](int t, int buf) {
        const int ty = (t & (TILES_Y - 1)) * TH;
        const int z  = t >> 7;                      // b*N + n
        const float* fb = frames + (size_t)z * plane;
        const uint32_t sb = sbase + (uint32_t)buf * (SBUF * 4);
        #pragma unroll
        for (int it = 0; it < 9; ++it) {
            const int idx = threadIdx.x + it * NT;
            if (idx < SH * SWP) {
                const int r = idx / SWP;
                const int c = idx - r * SWP;
                const int gy = ty + r - PC;
                const int gx = c - PC;
                const bool ok = (unsigned)gy < (unsigned)HC && (unsigned)gx < (unsigned)WC;
                const float* gp = ok ? (fb + (size_t)gy * WC + gx) : fb;
                cp4(sb + (uint32_t)idx * 4, gp, ok);
            }
        }
        asm volatile("cp.async.commit_group;\n");
    };

    // Thread -> output mapping: 4 rows x 128 float4-groups per tile.
    const int row = threadIdx.x >> 7;            // 0..3
    const int xx  = (threadIdx.x & 127) << 2;    // 0..508

    int t = blockIdx.x;
    if (t >= N_TILES) return;
    stage(t, 0);
    int buf = 0;

    while (t < N_TILES) {
        // steal next tile (one thread), then make current buffer visible
        if (threadIdx.x == 0) s_next = atomicAdd(&g_next, 1);
        asm volatile("cp.async.wait_group 0;\n");
        __syncthreads();
        const int tn = s_next;

        // prefetch next tile into the other buffer (overlaps compute below)
        if (tn < N_TILES) stage(tn, buf ^ 1);

        // ---- compute current tile ----
        const int ty = (t & (TILES_Y - 1)) * TH;
        const int z  = t >> 7;
        const int gy = ty + row;
        const size_t pix = (size_t)gy * WC + xx;

        const float* cbase = core + (size_t)z * (KC * KC) * plane;
        const float* wbase = Wt  + (size_t)z * plane;
        float*       obase = out + (size_t)z * plane;

        // W: read-once, issue early so its latency overlaps the core burst
        const float4 wv = __ldcs(reinterpret_cast<const float4*>(wbase + pix));

        const float* sb = &s[buf][0];
        float acc0 = 0.f, acc1 = 0.f, acc2 = 0.f, acc3 = 0.f;

        // Register-slim hot loop: per i, reload the 8-float window row from
        // smem (LDS), then 5 x (LDG.128 core + 4 FMA). Live regs ~40 ->
        // 3 CTAs/SM; latency hiding via warp count instead of burst depth.
        #pragma unroll
        for (int i = 0; i < KC; ++i) {
            const float* srow = sb + (row + i) * SWP + xx;
            const float4 a  = *reinterpret_cast<const float4*>(srow);
            const float4 bq = *reinterpret_cast<const float4*>(srow + 4);
            const float w[8] = { a.x, a.y, a.z, a.w, bq.x, bq.y, bq.z, bq.w };
            #pragma unroll
            for (int j = 0; j < KC; ++j) {
                const int k = i * KC + j;
                const float4 cv = __ldcs(
                    reinterpret_cast<const float4*>(cbase + (size_t)k * plane + pix));
                acc0 = fmaf(cv.x, w[j + 0], acc0);
                acc1 = fmaf(cv.y, w[j + 1], acc1);
                acc2 = fmaf(cv.z, w[j + 2], acc2);
                acc3 = fmaf(cv.w, w[j + 3], acc3);
            }
        }

        float4 o;
        o.x = acc0 * wv.x;
        o.y = acc1 * wv.y;
        o.z = acc2 * wv.z;
        o.w = acc3 * wv.w;
        __stcs(reinterpret_cast<float4*>(obase + pix), o);

        t = tn;
        buf ^= 1;
    }
}

extern "C" void kernel_launch(void* const* d_in, const int* in_sizes, int n_in,
                              void* d_out, int out_size)
{
    const float* frames = (const float*)d_in[0];
    const float* core   = (const float*)d_in[1];
    const float* Wt     = (const float*)d_in[2];
    float* out          = (float*)d_out;

    init_counter<<<1, 1>>>();
    kconv_kernel<<<GRID, NT>>>(frames, core, Wt, out);
}

// round 9
// speedup vs baseline: 1.0428x; 1.0428x over previous
#include <cuda_runtime.h>
#include <cstdint>

// Problem constants
constexpr int KC = 5, PC = 2, BC = 2, NC = 8, HC = 512, WC = 512;

// Full-width tiles: 4 rows x 512 cols. Each core-plane read per tile is one
// CONTIGUOUS 8KB block (4 rows x 2KB) -> maximal DRAM page locality for the
// 25 read-once core streams. Persistent CTAs, static strided schedule
// (no init kernel, no atomic ticket), cp.async double-buffered staging.
constexpr int TH = 4;
constexpr int SWP = 520;             // padded row pitch (floats), 16B aligned
constexpr int NT = 512;              // threads per CTA
constexpr int TILES_Y = HC / TH;     // 128 row-tiles
constexpr int N_TILES = TILES_Y * BC * NC;   // 2048
constexpr int GRID = 304;            // 152 SM x 2 CTAs, persistent
constexpr int SH = TH + 2 * PC;      // 8 staged rows
constexpr int SBUF = SH * SWP;       // 4160 floats per buffer

// cp.async 4B with zero-fill when !ok (src-size 0 -> no global read, zeros)
__device__ __forceinline__ void cp4(uint32_t dst, const float* src, bool ok) {
    asm volatile("cp.async.ca.shared.global [%0], [%1], 4, %2;\n"
                 :: "r"(dst), "l"(src), "r"(ok ? 4 : 0));
}

__global__ __launch_bounds__(NT, 2)
void kconv_kernel(const float* __restrict__ frames,
                  const float* __restrict__ core,
                  const float* __restrict__ Wt,
                  float* __restrict__ out)
{
    __shared__ float s[2][SBUF];

    const size_t plane = (size_t)HC * WC;
    const uint32_t sbase = (uint32_t)__cvta_generic_to_shared(&s[0][0]);

    // ---- async stage of one padded 8x520 frame strip into a smem buffer ----
    auto stage = [&](int t, int buf) {
        const int ty = (t & (TILES_Y - 1)) * TH;
        const int z  = t >> 7;                      // b*N + n
        const float* fb = frames + (size_t)z * plane;
        const uint32_t sb = sbase + (uint32_t)buf * (SBUF * 4);
        #pragma unroll
        for (int it = 0; it < 9; ++it) {
            const int idx = threadIdx.x + it * NT;
            if (idx < SH * SWP) {
                const int r = idx / SWP;
                const int c = idx - r * SWP;
                const int gy = ty + r - PC;
                const int gx = c - PC;
                const bool ok = (unsigned)gy < (unsigned)HC && (unsigned)gx < (unsigned)WC;
                const float* gp = ok ? (fb + (size_t)gy * WC + gx) : fb;
                cp4(sb + (uint32_t)idx * 4, gp, ok);
            }
        }
        asm volatile("cp.async.commit_group;\n");
    };

    // Thread -> output mapping: 4 rows x 128 float4-groups per tile.
    const int row = threadIdx.x >> 7;            // 0..3
    const int xx  = (threadIdx.x & 127) << 2;    // 0..508

    int t = blockIdx.x;
    if (t >= N_TILES) return;
    stage(t, 0);
    int buf = 0;

    while (t < N_TILES) {
        const int tn = t + GRID;                 // static strided schedule

        // make current buffer visible, then prefetch the next tile into the
        // other buffer (overlaps the compute below)
        asm volatile("cp.async.wait_group 0;\n");
        __syncthreads();
        if (tn < N_TILES) stage(tn, buf ^ 1);

        // ---- compute current tile ----
        const int ty = (t & (TILES_Y - 1)) * TH;
        const int z  = t >> 7;
        const int gy = ty + row;
        const size_t pix = (size_t)gy * WC + xx;

        const float* cbase = core + (size_t)z * (KC * KC) * plane;
        const float* wbase = Wt  + (size_t)z * plane;
        float*       obase = out + (size_t)z * plane;

        // W: read-once, issue early so its latency overlaps the core burst
        const float4 wv = __ldcs(reinterpret_cast<const float4*>(wbase + pix));

        // Preload the 5x8 frame window (pure LDS phase), then pure LDG->FMA.
        const float* sb = &s[buf][0];
        float w[KC][8];
        #pragma unroll
        for (int i = 0; i < KC; ++i) {
            const float* srow = sb + (row + i) * SWP + xx;
            const float4 a  = *reinterpret_cast<const float4*>(srow);
            const float4 bq = *reinterpret_cast<const float4*>(srow + 4);
            w[i][0] = a.x;  w[i][1] = a.y;  w[i][2] = a.z;  w[i][3] = a.w;
            w[i][4] = bq.x; w[i][5] = bq.y; w[i][6] = bq.z; w[i][7] = bq.w;
        }

        float acc0 = 0.f, acc1 = 0.f, acc2 = 0.f, acc3 = 0.f;
        #pragma unroll
        for (int i = 0; i < KC; ++i) {
            #pragma unroll
            for (int j = 0; j < KC; ++j) {
                const int k = i * KC + j;
                const float4 cv = __ldcs(
                    reinterpret_cast<const float4*>(cbase + (size_t)k * plane + pix));
                acc0 = fmaf(cv.x, w[i][j + 0], acc0);
                acc1 = fmaf(cv.y, w[i][j + 1], acc1);
                acc2 = fmaf(cv.z, w[i][j + 2], acc2);
                acc3 = fmaf(cv.w, w[i][j + 3], acc3);
            }
        }

        float4 o;
        o.x = acc0 * wv.x;
        o.y = acc1 * wv.y;
        o.z = acc2 * wv.z;
        o.w = acc3 * wv.w;
        __stcs(reinterpret_cast<float4*>(obase + pix), o);

        t = tn;
        buf ^= 1;
    }
}

extern "C" void kernel_launch(void* const* d_in, const int* in_sizes, int n_in,
                              void* d_out, int out_size)
{
    const float* frames = (const float*)d_in[0];
    const float* core   = (const float*)d_in[1];
    const float* Wt     = (const float*)d_in[2];
    float* out          = (float*)d_out;

    kconv_kernel<<<GRID, NT>>>(frames, core, Wt, out);
}